// round 6
// baseline (speedup 1.0000x reference)
#include <cuda_runtime.h>
#include <cuda_fp16.h>
#include <math.h>

#define S   256
#define Hd  512
#define E   64
#define R   32
#define L   9
#define BMAX 1024

typedef unsigned long long u64;

// Scratch (device globals; no allocation allowed)
__device__ float g_H[4 * BMAX * Hd];     // tanh(x@W1+b1) for modules {e0, r0, r1, r2}
__device__ float g_e02[2 * BMAX * E];    // split-K partials of e0
__device__ float g_r2[2 * 3 * BMAX * R]; // split-K partials of r

// ---------------------------------------------------------------------------
// Packed f32x2 helpers (Blackwell FFMA2 — ptxas never emits this from C++)
// ---------------------------------------------------------------------------
__device__ __forceinline__ u64 pk2(float x, float y) {
    u64 r;
    asm("mov.b64 %0, {%1, %2};" : "=l"(r) : "f"(x), "f"(y));
    return r;
}
__device__ __forceinline__ void fma2(u64& d, u64 a, u64 b) {
    asm("fma.rn.f32x2 %0, %1, %2, %0;" : "+l"(d) : "l"(a), "l"(b));
}
__device__ __forceinline__ u64 mul2(u64 a, u64 b) {
    u64 d;
    asm("mul.rn.f32x2 %0, %1, %2;" : "=l"(d) : "l"(a), "l"(b));
    return d;
}
__device__ __forceinline__ float2 upk(u64 v) {
    float2 f;
    asm("mov.b64 {%0, %1}, %2;" : "=f"(f.x), "=f"(f.y) : "l"(v));
    return f;
}

// ---------------------------------------------------------------------------
// Kernel 1: H = tanh(x @ W1 + b1) ; GEMM M=B, N=4*512, K=256
// 32x64 tiles, 128 threads, 4x4 micro via FFMA2, double-buffered smem.
// ---------------------------------------------------------------------------
__global__ __launch_bounds__(128) void k1_gemm_tanh(
    const float* __restrict__ x,
    const float* __restrict__ eW1, const float* __restrict__ eb1,
    const float* __restrict__ rW1, const float* __restrict__ rb1,
    int B)
{
    const int bn = blockIdx.x;
    const int bm = blockIdx.y;
    const int m  = bn >> 3;
    const int cb = (bn & 7) * 64;
    const float* W    = (m == 0) ? eW1 : (rW1 + (size_t)(m - 1) * S * Hd);
    const float* bias = (m == 0) ? eb1 : (rb1 + (size_t)(m - 1) * Hd);

    __shared__ float As[2][16][36];
    __shared__ float Bs[2][16][68];

    const int tid = threadIdx.x;
    const int tx = tid & 15;
    const int ty = tid >> 4;
    const int rowBase = bm * 32;

    const int a_row = tid >> 2;
    const int a_q   = tid & 3;
    const int w_k   = tid >> 4;
    const int w_q   = tid & 15;

    u64 acc[4][2];
    #pragma unroll
    for (int i = 0; i < 4; i++) { acc[i][0] = 0ull; acc[i][1] = 0ull; }

    float4 av, wv0, wv1;
    av  = *(const float4*)&x[(size_t)(rowBase + a_row) * S + a_q * 4];
    wv0 = *(const float4*)&W[(size_t)(w_k)     * Hd + cb + w_q * 4];
    wv1 = *(const float4*)&W[(size_t)(w_k + 8) * Hd + cb + w_q * 4];

    int buf = 0;
    As[0][a_q * 4 + 0][a_row] = av.x;
    As[0][a_q * 4 + 1][a_row] = av.y;
    As[0][a_q * 4 + 2][a_row] = av.z;
    As[0][a_q * 4 + 3][a_row] = av.w;
    *(float4*)&Bs[0][w_k][w_q * 4]     = wv0;
    *(float4*)&Bs[0][w_k + 8][w_q * 4] = wv1;
    __syncthreads();

    for (int c = 0; c < 16; c++) {
        if (c < 15) {
            const int k0 = (c + 1) * 16;
            av  = *(const float4*)&x[(size_t)(rowBase + a_row) * S + k0 + a_q * 4];
            wv0 = *(const float4*)&W[(size_t)(k0 + w_k)     * Hd + cb + w_q * 4];
            wv1 = *(const float4*)&W[(size_t)(k0 + w_k + 8) * Hd + cb + w_q * 4];
        }
        #pragma unroll
        for (int kk = 0; kk < 16; kk++) {
            float4 a = *(const float4*)&As[buf][kk][ty * 4];
            float4 w = *(const float4*)&Bs[buf][kk][tx * 4];
            u64 wp0 = pk2(w.x, w.y);
            u64 wp1 = pk2(w.z, w.w);
            float av4[4] = {a.x, a.y, a.z, a.w};
            #pragma unroll
            for (int i = 0; i < 4; i++) {
                u64 ad = pk2(av4[i], av4[i]);
                fma2(acc[i][0], ad, wp0);
                fma2(acc[i][1], ad, wp1);
            }
        }
        if (c < 15) {
            const int nb = buf ^ 1;
            As[nb][a_q * 4 + 0][a_row] = av.x;
            As[nb][a_q * 4 + 1][a_row] = av.y;
            As[nb][a_q * 4 + 2][a_row] = av.z;
            As[nb][a_q * 4 + 3][a_row] = av.w;
            *(float4*)&Bs[nb][w_k][w_q * 4]     = wv0;
            *(float4*)&Bs[nb][w_k + 8][w_q * 4] = wv1;
            __syncthreads();
            buf = nb;
        }
    }

    float bv[4];
    #pragma unroll
    for (int j = 0; j < 4; j++) bv[j] = bias[cb + tx * 4 + j];

    #pragma unroll
    for (int i = 0; i < 4; i++) {
        int row = rowBase + ty * 4 + i;
        #pragma unroll
        for (int p = 0; p < 2; p++) {
            float2 v = upk(acc[i][p]);
            int col = cb + tx * 4 + 2 * p;
            g_H[((size_t)m * B + row) * Hd + col]     = tanhf(v.x + bv[2 * p]);
            g_H[((size_t)m * B + row) * Hd + col + 1] = tanhf(v.y + bv[2 * p + 1]);
        }
    }
}

// ---------------------------------------------------------------------------
// Kernel 2: layer2 GEMM with split-K (2 chunks of 256). Partials summed in k3.
// ---------------------------------------------------------------------------
template<int O>
__device__ __forceinline__ void k2_body(
    const float* __restrict__ Hb, const float* __restrict__ W2,
    const float* __restrict__ bias, float* __restrict__ outp,
    int B, int kbeg, float* sm)
{
    constexpr int TX = O / 4;
    constexpr int RT = 32 * TX / 256;
    float* Hs = sm;
    float* Ws = sm + 32 * 36;

    const int tid = threadIdx.x;
    const int rowBase = blockIdx.x * 32;
    const int tx = tid % TX;
    const int ty = tid / TX;

    const int h_row = tid >> 3;
    const int h_q   = tid & 7;

    float acc[RT][4];
    #pragma unroll
    for (int i = 0; i < RT; i++)
        #pragma unroll
        for (int j = 0; j < 4; j++) acc[i][j] = 0.0f;

    for (int k0 = kbeg; k0 < kbeg + 256; k0 += 32) {
        float4 hv = *(const float4*)&Hb[(size_t)(rowBase + h_row) * Hd + k0 + h_q * 4];
        float4 wv[2];
        #pragma unroll
        for (int it = 0; it < (8 * O) / 256; it++) {
            int i = tid + it * 256;
            int k  = i / TX;
            int n4 = i % TX;
            wv[it] = *(const float4*)&W2[(size_t)(k0 + k) * O + n4 * 4];
        }
        __syncthreads();
        Hs[(h_q * 4 + 0) * 36 + h_row] = hv.x;
        Hs[(h_q * 4 + 1) * 36 + h_row] = hv.y;
        Hs[(h_q * 4 + 2) * 36 + h_row] = hv.z;
        Hs[(h_q * 4 + 3) * 36 + h_row] = hv.w;
        #pragma unroll
        for (int it = 0; it < (8 * O) / 256; it++) {
            int i = tid + it * 256;
            int k  = i / TX;
            int n4 = i % TX;
            *(float4*)&Ws[k * (O + 4) + n4 * 4] = wv[it];
        }
        __syncthreads();
        #pragma unroll
        for (int kk = 0; kk < 32; kk++) {
            float a[RT];
            #pragma unroll
            for (int i = 0; i < RT; i++) a[i] = Hs[kk * 36 + ty * RT + i];
            float4 w = *(const float4*)&Ws[kk * (O + 4) + tx * 4];
            #pragma unroll
            for (int i = 0; i < RT; i++) {
                acc[i][0] += a[i] * w.x;
                acc[i][1] += a[i] * w.y;
                acc[i][2] += a[i] * w.z;
                acc[i][3] += a[i] * w.w;
            }
        }
    }

    float bv[4];
    #pragma unroll
    for (int j = 0; j < 4; j++) bv[j] = bias ? bias[tx * 4 + j] : 0.0f;
    #pragma unroll
    for (int i = 0; i < RT; i++) {
        int row = rowBase + ty * RT + i;
        #pragma unroll
        for (int j = 0; j < 4; j++)
            outp[(size_t)row * O + tx * 4 + j] = acc[i][j] + bv[j];
    }
}

__global__ __launch_bounds__(256) void k2_all(
    const float* __restrict__ eW2, const float* __restrict__ eb2,
    const float* __restrict__ rW2, const float* __restrict__ rb2, int B)
{
    extern __shared__ float sm2[];
    const int kz   = blockIdx.z;
    const int kbeg = kz * 256;
    if (blockIdx.y == 0) {
        k2_body<64>(g_H, eW2, kz ? nullptr : eb2,
                    g_e02 + (size_t)kz * B * E, B, kbeg, sm2);
    } else {
        int km = blockIdx.y - 1;
        k2_body<32>(g_H + (size_t)(1 + km) * B * Hd,
                    rW2 + (size_t)km * Hd * R, kz ? nullptr : (rb2 + km * R),
                    g_r2 + (size_t)kz * 3 * B * R + (size_t)km * B * R,
                    B, kbeg, sm2);
    }
}

// ---------------------------------------------------------------------------
// Kernel 3 (fused, single-wave): one CTA per batch, 128 threads, occ 8.
// During the single tpr[b] stream:
//   v1[f]  = sum_{e,r} e0[e]*r0[r]*tpr[b,e,r,f]   (rank-1, fp32 exact)
//   A1[e,f]= sum_r r1[r]*tpr  -> smem fp32 (16KB)
//   A2[e,f]= sum_r r2[r]*tpr  -> smem fp16 (8KB; only feeds i3)
// Then chain: i1=LN(v1); i2=LN(i1@A1); i3=LN(i2@A2); out=(i1+i2+i3)@Z.
// smem ~26KB, regs<=64 -> 8 CTAs/SM -> 1184 slots >= 1024 CTAs = ONE wave.
// ---------------------------------------------------------------------------
__global__ __launch_bounds__(128, 8) void k3_fused(
    const float* __restrict__ tpr,
    const float* __restrict__ ln_g, const float* __restrict__ ln_b,
    const float* __restrict__ Z,
    float* __restrict__ out, int B)
{
    extern __shared__ char smraw[];
    float*  A1s  = (float*)smraw;                 // 4096 floats (16KB)
    float2* srv2 = (float2*)(A1s + 4096);         // 96
    float2* se0  = srv2 + 96;                     // 64
    float*  sv1  = (float*)(se0 + 64);            // 64
    float*  scur = sv1 + 64;                      // 64
    float*  ssum = scur + 64;                     // 64
    float*  sred = ssum + 64;                     // 4
    __half* A2h  = (__half*)(sred + 4);           // 4096 halves (8KB)

    const int b   = blockIdx.x;
    const int tid = threadIdx.x;

    if (tid < 96) {
        const int k = tid >> 5, j = tid & 31;
        size_t idx = ((size_t)k * B + b) * R + j;
        float v = g_r2[idx] + g_r2[(size_t)3 * B * R + idx];
        srv2[tid] = make_float2(v, v);
    }
    if (tid < 64) {
        float v = g_e02[(size_t)b * E + tid] + g_e02[(size_t)B * E + (size_t)b * E + tid];
        se0[tid] = make_float2(v, v);
        sv1[tid] = 0.0f;
        ssum[tid] = 0.0f;
    }
    __syncthreads();

    // --- streaming pass over tpr[b] (512 KB, read exactly once) ---
    const int f4 = tid & 15;      // float4 index along f
    const int eg = tid >> 4;      // 0..7
    u64 v01 = 0, v23 = 0;         // rank-1 partials (persist across e)
    #pragma unroll 1
    for (int j = 0; j < 8; j++) {
        const int e = j * 8 + eg;
        const float4* p = (const float4*)tpr + ((size_t)b * E + e) * (R * 16) + f4;
        const u64 pe = *(u64*)&se0[e];
        u64 a10 = 0, a11 = 0, a20 = 0, a21 = 0;
        #pragma unroll 1
        for (int rb = 0; rb < 8; rb++) {
            float4 buf[4];
            #pragma unroll
            for (int u = 0; u < 4; u++)
                buf[u] = __ldcs(&p[(size_t)(rb * 4 + u) * 16]);
            #pragma unroll
            for (int u = 0; u < 4; u++) {
                const int r = rb * 4 + u;
                u64 t01 = pk2(buf[u].x, buf[u].y);
                u64 t23 = pk2(buf[u].z, buf[u].w);
                u64 c0 = *(u64*)&srv2[r];
                u64 c1 = *(u64*)&srv2[32 + r];
                u64 c2 = *(u64*)&srv2[64 + r];
                u64 ce = mul2(pe, c0);
                fma2(v01, ce, t01); fma2(v23, ce, t23);
                fma2(a10, c1, t01); fma2(a11, c1, t23);
                fma2(a20, c2, t01); fma2(a21, c2, t23);
            }
        }
        *(float2*)&A1s[e * 64 + f4 * 4]     = upk(a10);
        *(float2*)&A1s[e * 64 + f4 * 4 + 2] = upk(a11);
        *(__half2*)&A2h[e * 64 + f4 * 4]     = __float22half2_rn(upk(a20));
        *(__half2*)&A2h[e * 64 + f4 * 4 + 2] = __float22half2_rn(upk(a21));
    }
    {
        float2 a = upk(v01), c = upk(v23);
        atomicAdd(&sv1[f4 * 4 + 0], a.x);
        atomicAdd(&sv1[f4 * 4 + 1], a.y);
        atomicAdd(&sv1[f4 * 4 + 2], c.x);
        atomicAdd(&sv1[f4 * 4 + 3], c.y);
    }
    __syncthreads();

    // --- chain (2 warps active) ---
    for (int step = 0; step < 3; step++) {
        float sval = 0.0f;
        if (tid < E) {
            if (step == 0) {
                sval = sv1[tid];
            } else if (step == 1) {
                #pragma unroll 16
                for (int e = 0; e < E; e++) sval += scur[e] * A1s[e * 64 + tid];
            } else {
                #pragma unroll 16
                for (int e = 0; e < E; e++) sval += scur[e] * __half2float(A2h[e * 64 + tid]);
            }
            float s1 = sval, s2 = sval * sval;
            #pragma unroll
            for (int o = 16; o; o >>= 1) {
                s1 += __shfl_xor_sync(0xffffffffu, s1, o);
                s2 += __shfl_xor_sync(0xffffffffu, s2, o);
            }
            if ((tid & 31) == 0) { sred[(tid >> 5) * 2] = s1; sred[(tid >> 5) * 2 + 1] = s2; }
        }
        __syncthreads();
        if (tid < E) {
            float s1 = sred[0] + sred[2];
            float s2 = sred[1] + sred[3];
            float mu  = s1 * (1.0f / 64.0f);
            float var = s2 * (1.0f / 64.0f) - mu * mu;
            float inv = rsqrtf(var + 1e-6f);
            float iv  = ln_g[step * E + tid] * (sval - mu) * inv + ln_b[step * E + tid];
            scur[tid] = iv;
            ssum[tid] += iv;
        }
        __syncthreads();
    }

    if (tid < L) {
        float acc = 0.0f;
        #pragma unroll 8
        for (int f = 0; f < E; f++) acc += ssum[f] * Z[f * L + tid];
        out[(size_t)b * L + tid] = acc;
    }
}

// ---------------------------------------------------------------------------
extern "C" void kernel_launch(void* const* d_in, const int* in_sizes, int n_in,
                              void* d_out, int out_size)
{
    const float* x    = (const float*)d_in[0];
    const float* tpr  = (const float*)d_in[1];
    const float* eW1  = (const float*)d_in[2];
    const float* eb1  = (const float*)d_in[3];
    const float* eW2  = (const float*)d_in[4];
    const float* eb2  = (const float*)d_in[5];
    const float* rW1  = (const float*)d_in[6];
    const float* rb1  = (const float*)d_in[7];
    const float* rW2  = (const float*)d_in[8];
    const float* rb2  = (const float*)d_in[9];
    const float* ln_g = (const float*)d_in[10];
    const float* ln_b = (const float*)d_in[11];
    const float* Z    = (const float*)d_in[12];
    float* out = (float*)d_out;

    int B = in_sizes[0] / S;   // 1024

    dim3 g1(32, B / 32);
    k1_gemm_tanh<<<g1, 128>>>(x, eW1, eb1, rW1, rb1, B);

    dim3 g2(B / 32, 4, 2);
    size_t smem2 = (size_t)(32 * 36 + 32 * 68) * sizeof(float);
    k2_all<<<g2, 256, smem2>>>(eW2, eb2, rW2, rb2, B);

    size_t smem3 = 4096 * sizeof(float)            // A1
                 + 160 * sizeof(float2)            // srv2 + se0
                 + (64 * 3 + 4) * sizeof(float)    // sv1, scur, ssum, sred
                 + 4096 * sizeof(__half);          // A2
    k3_fused<<<B, 128, smem3>>>(tpr, ln_g, ln_b, Z, out, B);
}

// round 7
// speedup vs baseline: 1.0953x; 1.0953x over previous
#include <cuda_runtime.h>
#include <cuda_fp16.h>
#include <math.h>

#define S   256
#define Hd  512
#define E   64
#define R   32
#define L   9
#define BMAX 1024

typedef unsigned long long u64;

// Scratch (device globals; no allocation allowed)
__device__ float  g_H[4 * BMAX * Hd];      // tanh(x@W1+b1) for {e0, r0, r1, r2}
__device__ float  g_e02[2 * BMAX * E];     // split-K partials of e0
__device__ float  g_r2[2 * 3 * BMAX * R];  // split-K partials of r
__device__ __half g_A1h[(size_t)BMAX * E * E];  // A1[b][e][f] fp16
__device__ __half g_A2h[(size_t)BMAX * E * E];  // A2[b][e][f] fp16
__device__ float  g_v1p[(size_t)BMAX * 4 * E];  // per-quarter partials of v1

// ---------------------------------------------------------------------------
// Packed f32x2 helpers (Blackwell FFMA2 — ptxas never emits this from C++)
// ---------------------------------------------------------------------------
__device__ __forceinline__ u64 pk2(float x, float y) {
    u64 r;
    asm("mov.b64 %0, {%1, %2};" : "=l"(r) : "f"(x), "f"(y));
    return r;
}
__device__ __forceinline__ void fma2(u64& d, u64 a, u64 b) {
    asm("fma.rn.f32x2 %0, %1, %2, %0;" : "+l"(d) : "l"(a), "l"(b));
}
__device__ __forceinline__ u64 mul2(u64 a, u64 b) {
    u64 d;
    asm("mul.rn.f32x2 %0, %1, %2;" : "=l"(d) : "l"(a), "l"(b));
    return d;
}
__device__ __forceinline__ float2 upk(u64 v) {
    float2 f;
    asm("mov.b64 {%0, %1}, %2;" : "=f"(f.x), "=f"(f.y) : "l"(v));
    return f;
}

// ---------------------------------------------------------------------------
// Kernel 1: H = tanh(x @ W1 + b1) ; GEMM M=B, N=4*512, K=256
// 32x64 tiles, 128 threads, 4x4 micro via FFMA2, double-buffered smem.
// ---------------------------------------------------------------------------
__global__ __launch_bounds__(128) void k1_gemm_tanh(
    const float* __restrict__ x,
    const float* __restrict__ eW1, const float* __restrict__ eb1,
    const float* __restrict__ rW1, const float* __restrict__ rb1,
    int B)
{
    const int bn = blockIdx.x;
    const int bm = blockIdx.y;
    const int m  = bn >> 3;
    const int cb = (bn & 7) * 64;
    const float* W    = (m == 0) ? eW1 : (rW1 + (size_t)(m - 1) * S * Hd);
    const float* bias = (m == 0) ? eb1 : (rb1 + (size_t)(m - 1) * Hd);

    __shared__ float As[2][16][36];
    __shared__ float Bs[2][16][68];

    const int tid = threadIdx.x;
    const int tx = tid & 15;
    const int ty = tid >> 4;
    const int rowBase = bm * 32;

    const int a_row = tid >> 2;
    const int a_q   = tid & 3;
    const int w_k   = tid >> 4;
    const int w_q   = tid & 15;

    u64 acc[4][2];
    #pragma unroll
    for (int i = 0; i < 4; i++) { acc[i][0] = 0ull; acc[i][1] = 0ull; }

    float4 av, wv0, wv1;
    av  = *(const float4*)&x[(size_t)(rowBase + a_row) * S + a_q * 4];
    wv0 = *(const float4*)&W[(size_t)(w_k)     * Hd + cb + w_q * 4];
    wv1 = *(const float4*)&W[(size_t)(w_k + 8) * Hd + cb + w_q * 4];

    int buf = 0;
    As[0][a_q * 4 + 0][a_row] = av.x;
    As[0][a_q * 4 + 1][a_row] = av.y;
    As[0][a_q * 4 + 2][a_row] = av.z;
    As[0][a_q * 4 + 3][a_row] = av.w;
    *(float4*)&Bs[0][w_k][w_q * 4]     = wv0;
    *(float4*)&Bs[0][w_k + 8][w_q * 4] = wv1;
    __syncthreads();

    for (int c = 0; c < 16; c++) {
        if (c < 15) {
            const int k0 = (c + 1) * 16;
            av  = *(const float4*)&x[(size_t)(rowBase + a_row) * S + k0 + a_q * 4];
            wv0 = *(const float4*)&W[(size_t)(k0 + w_k)     * Hd + cb + w_q * 4];
            wv1 = *(const float4*)&W[(size_t)(k0 + w_k + 8) * Hd + cb + w_q * 4];
        }
        #pragma unroll
        for (int kk = 0; kk < 16; kk++) {
            float4 a = *(const float4*)&As[buf][kk][ty * 4];
            float4 w = *(const float4*)&Bs[buf][kk][tx * 4];
            u64 wp0 = pk2(w.x, w.y);
            u64 wp1 = pk2(w.z, w.w);
            float av4[4] = {a.x, a.y, a.z, a.w};
            #pragma unroll
            for (int i = 0; i < 4; i++) {
                u64 ad = pk2(av4[i], av4[i]);
                fma2(acc[i][0], ad, wp0);
                fma2(acc[i][1], ad, wp1);
            }
        }
        if (c < 15) {
            const int nb = buf ^ 1;
            As[nb][a_q * 4 + 0][a_row] = av.x;
            As[nb][a_q * 4 + 1][a_row] = av.y;
            As[nb][a_q * 4 + 2][a_row] = av.z;
            As[nb][a_q * 4 + 3][a_row] = av.w;
            *(float4*)&Bs[nb][w_k][w_q * 4]     = wv0;
            *(float4*)&Bs[nb][w_k + 8][w_q * 4] = wv1;
            __syncthreads();
            buf = nb;
        }
    }

    float bv[4];
    #pragma unroll
    for (int j = 0; j < 4; j++) bv[j] = bias[cb + tx * 4 + j];

    #pragma unroll
    for (int i = 0; i < 4; i++) {
        int row = rowBase + ty * 4 + i;
        #pragma unroll
        for (int p = 0; p < 2; p++) {
            float2 v = upk(acc[i][p]);
            int col = cb + tx * 4 + 2 * p;
            g_H[((size_t)m * B + row) * Hd + col]     = tanhf(v.x + bv[2 * p]);
            g_H[((size_t)m * B + row) * Hd + col + 1] = tanhf(v.y + bv[2 * p + 1]);
        }
    }
}

// ---------------------------------------------------------------------------
// Kernel 2: layer2 GEMM with split-K (2 chunks of 256). Partials summed later.
// ---------------------------------------------------------------------------
template<int O>
__device__ __forceinline__ void k2_body(
    const float* __restrict__ Hb, const float* __restrict__ W2,
    const float* __restrict__ bias, float* __restrict__ outp,
    int B, int kbeg, float* sm)
{
    constexpr int TX = O / 4;
    constexpr int RT = 32 * TX / 256;
    float* Hs = sm;
    float* Ws = sm + 32 * 36;

    const int tid = threadIdx.x;
    const int rowBase = blockIdx.x * 32;
    const int tx = tid % TX;
    const int ty = tid / TX;

    const int h_row = tid >> 3;
    const int h_q   = tid & 7;

    float acc[RT][4];
    #pragma unroll
    for (int i = 0; i < RT; i++)
        #pragma unroll
        for (int j = 0; j < 4; j++) acc[i][j] = 0.0f;

    for (int k0 = kbeg; k0 < kbeg + 256; k0 += 32) {
        float4 hv = *(const float4*)&Hb[(size_t)(rowBase + h_row) * Hd + k0 + h_q * 4];
        float4 wv[2];
        #pragma unroll
        for (int it = 0; it < (8 * O) / 256; it++) {
            int i = tid + it * 256;
            int k  = i / TX;
            int n4 = i % TX;
            wv[it] = *(const float4*)&W2[(size_t)(k0 + k) * O + n4 * 4];
        }
        __syncthreads();
        Hs[(h_q * 4 + 0) * 36 + h_row] = hv.x;
        Hs[(h_q * 4 + 1) * 36 + h_row] = hv.y;
        Hs[(h_q * 4 + 2) * 36 + h_row] = hv.z;
        Hs[(h_q * 4 + 3) * 36 + h_row] = hv.w;
        #pragma unroll
        for (int it = 0; it < (8 * O) / 256; it++) {
            int i = tid + it * 256;
            int k  = i / TX;
            int n4 = i % TX;
            *(float4*)&Ws[k * (O + 4) + n4 * 4] = wv[it];
        }
        __syncthreads();
        #pragma unroll
        for (int kk = 0; kk < 32; kk++) {
            float a[RT];
            #pragma unroll
            for (int i = 0; i < RT; i++) a[i] = Hs[kk * 36 + ty * RT + i];
            float4 w = *(const float4*)&Ws[kk * (O + 4) + tx * 4];
            #pragma unroll
            for (int i = 0; i < RT; i++) {
                acc[i][0] += a[i] * w.x;
                acc[i][1] += a[i] * w.y;
                acc[i][2] += a[i] * w.z;
                acc[i][3] += a[i] * w.w;
            }
        }
    }

    float bv[4];
    #pragma unroll
    for (int j = 0; j < 4; j++) bv[j] = bias ? bias[tx * 4 + j] : 0.0f;
    #pragma unroll
    for (int i = 0; i < RT; i++) {
        int row = rowBase + ty * RT + i;
        #pragma unroll
        for (int j = 0; j < 4; j++)
            outp[(size_t)row * O + tx * 4 + j] = acc[i][j] + bv[j];
    }
}

__global__ __launch_bounds__(256) void k2_all(
    const float* __restrict__ eW2, const float* __restrict__ eb2,
    const float* __restrict__ rW2, const float* __restrict__ rb2, int B)
{
    extern __shared__ float sm2[];
    const int kz   = blockIdx.z;
    const int kbeg = kz * 256;
    if (blockIdx.y == 0) {
        k2_body<64>(g_H, eW2, kz ? nullptr : eb2,
                    g_e02 + (size_t)kz * B * E, B, kbeg, sm2);
    } else {
        int km = blockIdx.y - 1;
        k2_body<32>(g_H + (size_t)(1 + km) * B * Hd,
                    rW2 + (size_t)km * Hd * R, kz ? nullptr : (rb2 + km * R),
                    g_r2 + (size_t)kz * 3 * B * R + (size_t)km * B * R,
                    B, kbeg, sm2);
    }
}

// ---------------------------------------------------------------------------
// Kernel 3a: streaming contraction (proven 6.6 TB/s config). One CTA per
// (batch, e-quarter of 16), 256 threads, buf[8]. During the stream:
//   v1 partial (rank-1 with e0[e]*r0[r], fp32)  -> g_v1p
//   A1[e][f] fp16 -> g_A1h ; A2[e][f] fp16 -> g_A2h
// ---------------------------------------------------------------------------
__global__ __launch_bounds__(256) void k3a_contract(
    const float* __restrict__ tpr, int B)
{
    __shared__ float2 srv2[96];
    __shared__ float  se0[16];
    __shared__ float  stmp[8 * 64];

    const int b = blockIdx.x >> 2;
    const int q = blockIdx.x & 3;
    const int tid = threadIdx.x;

    if (tid < 96) {
        const int k = tid >> 5, j = tid & 31;
        size_t idx = ((size_t)k * B + b) * R + j;
        float v = g_r2[idx] + g_r2[(size_t)3 * B * R + idx];
        srv2[tid] = make_float2(v, v);
    }
    if (tid < 16) {
        int e = q * 16 + tid;
        se0[tid] = g_e02[(size_t)b * E + e] + g_e02[(size_t)B * E + (size_t)b * E + e];
    }
    __syncthreads();

    const int el = tid >> 4;
    const int e  = q * 16 + el;
    const int f4 = tid & 15;
    const float4* p = (const float4*)tpr + ((size_t)b * E + e) * (R * 16) + f4;
    const u64 pe = pk2(se0[el], se0[el]);

    u64 v01 = 0, v23 = 0, a10 = 0, a11 = 0, a20 = 0, a21 = 0;
    #pragma unroll 1
    for (int rb = 0; rb < 4; rb++) {
        float4 buf[8];
        #pragma unroll
        for (int u = 0; u < 8; u++)
            buf[u] = __ldcs(&p[(size_t)(rb * 8 + u) * 16]);
        #pragma unroll
        for (int u = 0; u < 8; u++) {
            const int r = rb * 8 + u;
            u64 t01 = pk2(buf[u].x, buf[u].y);
            u64 t23 = pk2(buf[u].z, buf[u].w);
            u64 c0 = *(u64*)&srv2[r];
            u64 c1 = *(u64*)&srv2[32 + r];
            u64 c2 = *(u64*)&srv2[64 + r];
            u64 ce = mul2(pe, c0);
            fma2(v01, ce, t01); fma2(v23, ce, t23);
            fma2(a10, c1, t01); fma2(a11, c1, t23);
            fma2(a20, c2, t01); fma2(a21, c2, t23);
        }
    }

    // fp16 A writes (coalesced: 8B per thread, consecutive in f)
    {
        __half2 h0 = __float22half2_rn(upk(a10));
        __half2 h1 = __float22half2_rn(upk(a11));
        *(__half2*)&g_A1h[(size_t)b * E * E + e * E + f4 * 4]     = h0;
        *(__half2*)&g_A1h[(size_t)b * E * E + e * E + f4 * 4 + 2] = h1;
        h0 = __float22half2_rn(upk(a20));
        h1 = __float22half2_rn(upk(a21));
        *(__half2*)&g_A2h[(size_t)b * E * E + e * E + f4 * 4]     = h0;
        *(__half2*)&g_A2h[(size_t)b * E * E + e * E + f4 * 4 + 2] = h1;
    }

    // deterministic v1 reduction over the 16 e's of this CTA
    {
        float2 a = upk(v01), c = upk(v23);
        a.x += __shfl_xor_sync(0xffffffffu, a.x, 16);
        a.y += __shfl_xor_sync(0xffffffffu, a.y, 16);
        c.x += __shfl_xor_sync(0xffffffffu, c.x, 16);
        c.y += __shfl_xor_sync(0xffffffffu, c.y, 16);
        if ((tid & 31) < 16) {
            const int w = tid >> 5;
            *(float4*)&stmp[w * 64 + (tid & 15) * 4] = make_float4(a.x, a.y, c.x, c.y);
        }
    }
    __syncthreads();
    if (tid < 64) {
        float s = 0.0f;
        #pragma unroll
        for (int w = 0; w < 8; w++) s += stmp[w * 64 + tid];
        g_v1p[((size_t)b * 4 + q) * E + tid] = s;
    }
}

// ---------------------------------------------------------------------------
// Kernel 3b: chain. One CTA per batch, 128 threads, occ 8 (single wave).
// Stage A1h+A2h (16KB fp16, L2-resident), sum v1 partials, run LN chain, @Z.
// ---------------------------------------------------------------------------
__global__ __launch_bounds__(128, 8) void k3b_chain(
    const float* __restrict__ ln_g, const float* __restrict__ ln_b,
    const float* __restrict__ Z,
    float* __restrict__ out, int B)
{
    __shared__ __half A1h[E * E];
    __shared__ __half A2h[E * E];
    __shared__ float scur[64], ssum[64], sv1[64], sred[4];

    const int b   = blockIdx.x;
    const int tid = threadIdx.x;

    // stage: each matrix 8KB = 512 float4; 4 per thread per matrix
    {
        const float4* s1 = (const float4*)(g_A1h + (size_t)b * E * E);
        const float4* s2 = (const float4*)(g_A2h + (size_t)b * E * E);
        float4* d1 = (float4*)A1h;
        float4* d2 = (float4*)A2h;
        #pragma unroll
        for (int i = 0; i < 4; i++) {
            d1[tid + i * 128] = __ldg(&s1[tid + i * 128]);
            d2[tid + i * 128] = __ldg(&s2[tid + i * 128]);
        }
    }
    if (tid < 64) {
        float s = 0.0f;
        #pragma unroll
        for (int qq = 0; qq < 4; qq++)
            s += g_v1p[((size_t)b * 4 + qq) * E + tid];
        sv1[tid]  = s;
        ssum[tid] = 0.0f;
    }
    __syncthreads();

    for (int step = 0; step < 3; step++) {
        float sval = 0.0f;
        if (tid < E) {
            if (step == 0) {
                sval = sv1[tid];
            } else if (step == 1) {
                #pragma unroll 16
                for (int e = 0; e < E; e++) sval += scur[e] * __half2float(A1h[e * E + tid]);
            } else {
                #pragma unroll 16
                for (int e = 0; e < E; e++) sval += scur[e] * __half2float(A2h[e * E + tid]);
            }
            float s1 = sval, s2 = sval * sval;
            #pragma unroll
            for (int o = 16; o; o >>= 1) {
                s1 += __shfl_xor_sync(0xffffffffu, s1, o);
                s2 += __shfl_xor_sync(0xffffffffu, s2, o);
            }
            if ((tid & 31) == 0) { sred[(tid >> 5) * 2] = s1; sred[(tid >> 5) * 2 + 1] = s2; }
        }
        __syncthreads();
        if (tid < E) {
            float s1 = sred[0] + sred[2];
            float s2 = sred[1] + sred[3];
            float mu  = s1 * (1.0f / 64.0f);
            float var = s2 * (1.0f / 64.0f) - mu * mu;
            float inv = rsqrtf(var + 1e-6f);
            float iv  = ln_g[step * E + tid] * (sval - mu) * inv + ln_b[step * E + tid];
            scur[tid] = iv;
            ssum[tid] += iv;
        }
        __syncthreads();
    }

    if (tid < L) {
        float acc = 0.0f;
        #pragma unroll 8
        for (int f = 0; f < E; f++) acc += ssum[f] * Z[f * L + tid];
        out[(size_t)b * L + tid] = acc;
    }
}

// ---------------------------------------------------------------------------
extern "C" void kernel_launch(void* const* d_in, const int* in_sizes, int n_in,
                              void* d_out, int out_size)
{
    const float* x    = (const float*)d_in[0];
    const float* tpr  = (const float*)d_in[1];
    const float* eW1  = (const float*)d_in[2];
    const float* eb1  = (const float*)d_in[3];
    const float* eW2  = (const float*)d_in[4];
    const float* eb2  = (const float*)d_in[5];
    const float* rW1  = (const float*)d_in[6];
    const float* rb1  = (const float*)d_in[7];
    const float* rW2  = (const float*)d_in[8];
    const float* rb2  = (const float*)d_in[9];
    const float* ln_g = (const float*)d_in[10];
    const float* ln_b = (const float*)d_in[11];
    const float* Z    = (const float*)d_in[12];
    float* out = (float*)d_out;

    int B = in_sizes[0] / S;   // 1024

    dim3 g1(32, B / 32);
    k1_gemm_tanh<<<g1, 128>>>(x, eW1, eb1, rW1, rb1, B);

    dim3 g2(B / 32, 4, 2);
    size_t smem2 = (size_t)(32 * 36 + 32 * 68) * sizeof(float);
    k2_all<<<g2, 256, smem2>>>(eW2, eb2, rW2, rb2, B);

    k3a_contract<<<B * 4, 256>>>(tpr, B);

    k3b_chain<<<B, 128>>>(ln_g, ln_b, Z, out, B);
}